// round 4
// baseline (speedup 1.0000x reference)
#include <cuda_runtime.h>
#include <math.h>
#include <stdint.h>

#define N_NODES 12800
#define N_EDGES 204800
#define DIM 16

typedef unsigned long long ull;

// ---------------- scratch (static device memory, no allocs) ----------------
__device__ float g_out[N_NODES * DIM];
__device__ float g_he[N_EDGES * DIM];      // edge hidden, edge order
__device__ float g_hs[N_EDGES * DIM];      // edge hidden, src-sorted order
__device__ int   g_qs[N_EDGES];            // src-sorted slot -> dst-sorted slot
__device__ float g_msg[N_EDGES * DIM];     // messages in dst-sorted order
__device__ int   g_src_cnt[N_NODES];       // zero at load; re-zeroed by k_scatter
__device__ int   g_dst_cnt[N_NODES];
__device__ int   g_src_off[N_NODES + 1];
__device__ int   g_dst_off[N_NODES + 1];
__device__ int   g_src_cur[N_NODES];
__device__ int   g_dst_cur[N_NODES];
__device__ float g_invdeg[N_NODES];

// ---------------- setup ----------------
__global__ void k_prep(const float* __restrict__ x, const int* __restrict__ ei,
                       const float* __restrict__ ea,
                       const float* __restrict__ l0w, const float* __restrict__ l0b,
                       const float* __restrict__ n1w, const float* __restrict__ n1b) {
    int gb = blockIdx.x;
    if (gb < (N_EDGES * DIM) / 256) {
        int i = gb * 256 + threadIdx.x;
        int e = i >> 4, j = i & 15;
        float acc = n1b[j];
#pragma unroll
        for (int c = 0; c < 4; ++c) acc += ea[e * 4 + c] * n1w[j * 4 + c];
        g_he[i] = fmaxf(acc, 0.0f);
        if (j == 0) {
            atomicAdd(&g_src_cnt[ei[e]], 1);
            atomicAdd(&g_dst_cnt[ei[N_EDGES + e]], 1);
        }
    } else {
        int i = (gb - (N_EDGES * DIM) / 256) * 256 + threadIdx.x;
        int n = i >> 4, k = i & 15;
        float acc = l0b[k];
#pragma unroll
        for (int c = 0; c < 3; ++c) acc += x[n * 3 + c] * l0w[k * 3 + c];
        g_out[i] = fmaxf(acc, 0.0f);
    }
}

// Shuffle-based exclusive scan; block 0 = src, block 1 = dst (+invdeg).
__global__ void k_scan() {
    const int PER = 13;
    int which = blockIdx.x;
    int* cnt = which ? g_dst_cnt : g_src_cnt;
    int* off = which ? g_dst_off : g_src_off;
    int* cur = which ? g_dst_cur : g_src_cur;
    int tid = threadIdx.x, lane = tid & 31, wid = tid >> 5;
    int base = tid * PER;
    int c[PER];
    int local = 0;
#pragma unroll
    for (int i = 0; i < PER; ++i) {
        int idx = base + i;
        c[i] = (idx < N_NODES) ? cnt[idx] : 0;
        local += c[i];
    }
    int incl = local;
#pragma unroll
    for (int s = 1; s < 32; s <<= 1) {
        int v = __shfl_up_sync(0xffffffffu, incl, s);
        if (lane >= s) incl += v;
    }
    __shared__ int wsum[32];
    if (lane == 31) wsum[wid] = incl;
    __syncthreads();
    if (wid == 0) {
        int v = wsum[lane];
        int iv = v;
#pragma unroll
        for (int s = 1; s < 32; s <<= 1) {
            int t = __shfl_up_sync(0xffffffffu, iv, s);
            if (lane >= s) iv += t;
        }
        wsum[lane] = iv - v;
    }
    __syncthreads();
    int run = wsum[wid] + (incl - local);
#pragma unroll
    for (int i = 0; i < PER; ++i) {
        int idx = base + i;
        if (idx < N_NODES) {
            off[idx] = run;
            cur[idx] = run;
            if (which) g_invdeg[idx] = 1.0f / fmaxf((float)c[i], 1.0f);
            run += c[i];
        }
    }
    if (tid == 1023) off[N_NODES] = run;
}

// Place each edge: gather h_e into src-sorted order, record its dst slot.
// Re-zeroes count arrays for the next kernel_launch call.
__global__ void k_scatter(const int* __restrict__ ei) {
    int e = blockIdx.x * blockDim.x + threadIdx.x;
    if (e >= N_EDGES) return;
    int s = ei[e], d = ei[N_EDGES + e];
    int p = atomicAdd(&g_src_cur[s], 1);
    int q = atomicAdd(&g_dst_cur[d], 1);
    g_qs[p] = q;
    const float4* hsrc = (const float4*)&g_he[e * DIM];
    float4* hdst = (float4*)&g_hs[p * DIM];
    hdst[0] = hsrc[0]; hdst[1] = hsrc[1]; hdst[2] = hsrc[2]; hdst[3] = hsrc[3];
    if (e < N_NODES) { g_src_cnt[e] = 0; g_dst_cnt[e] = 0; }
}

// ---------------- per-round kernels ----------------
// k_msg: 256 threads = 16 nodes x 16 lanes; lane owns one k.
// P[k][j0..15] kept as 8 packed f32x2 registers. Streams the node's
// src-sorted edges: msg[k] = xb[k] + dot(h_e, P[k]); store to dst slot.
__global__ void __launch_bounds__(256) k_msg(const float* __restrict__ w2,
                                             const float* __restrict__ b2) {
    __shared__ ull s_w2p[16 * 8 * 16];   // [d][jj][k], j-pairs packed: 16 KB
    __shared__ float s_b2[256];          // [d][k]
    __shared__ float s_out[16][16];
    int tid = threadIdx.x;
    for (int i = tid; i < 4096; i += 256) {
        int d = i >> 8, k = (i >> 4) & 15, j = i & 15;
        ((float*)&s_w2p[(d * 8 + (j >> 1)) * 16 + k])[j & 1] = w2[i];
    }
    for (int i = tid; i < 256; i += 256) s_b2[i] = b2[i];
    int k = tid & 15, g = tid >> 4;
    int n = blockIdx.x * 16 + g;
    s_out[g][k] = g_out[n * DIM + k];
    __syncthreads();

    ull p2[8];
    float xb = 0.0f;
#pragma unroll
    for (int jj = 0; jj < 8; ++jj) p2[jj] = 0ull;
#pragma unroll
    for (int d = 0; d < 16; ++d) {
        float od = s_out[g][d];
        ull od2;
        asm("mov.b64 %0,{%1,%1};" : "=l"(od2) : "f"(od));
        xb += od * s_b2[d * 16 + k];
#pragma unroll
        for (int jj = 0; jj < 8; ++jj) {
            ull w = s_w2p[(d * 8 + jj) * 16 + k];
            asm("fma.rn.f32x2 %0,%1,%2,%0;" : "+l"(p2[jj]) : "l"(od2), "l"(w));
        }
    }

    int beg = g_src_off[n], end = g_src_off[n + 1];
    const ulonglong2* hsp = (const ulonglong2*)g_hs;
    for (int i = beg; i < end; ++i) {
        int q = __ldg(&g_qs[i]);
        ulonglong2 A = __ldg(&hsp[i * 4 + 0]);
        ulonglong2 B = __ldg(&hsp[i * 4 + 1]);
        ulonglong2 C = __ldg(&hsp[i * 4 + 2]);
        ulonglong2 D = __ldg(&hsp[i * 4 + 3]);
        ull acc;
        asm("mul.rn.f32x2 %0,%1,%2;" : "=l"(acc) : "l"(A.x), "l"(p2[0]));
        asm("fma.rn.f32x2 %0,%1,%2,%0;" : "+l"(acc) : "l"(A.y), "l"(p2[1]));
        asm("fma.rn.f32x2 %0,%1,%2,%0;" : "+l"(acc) : "l"(B.x), "l"(p2[2]));
        asm("fma.rn.f32x2 %0,%1,%2,%0;" : "+l"(acc) : "l"(B.y), "l"(p2[3]));
        asm("fma.rn.f32x2 %0,%1,%2,%0;" : "+l"(acc) : "l"(C.x), "l"(p2[4]));
        asm("fma.rn.f32x2 %0,%1,%2,%0;" : "+l"(acc) : "l"(C.y), "l"(p2[5]));
        asm("fma.rn.f32x2 %0,%1,%2,%0;" : "+l"(acc) : "l"(D.x), "l"(p2[6]));
        asm("fma.rn.f32x2 %0,%1,%2,%0;" : "+l"(acc) : "l"(D.y), "l"(p2[7]));
        float lo, hi;
        asm("mov.b64 {%0,%1},%2;" : "=f"(lo), "=f"(hi) : "l"(acc));
        g_msg[q * DIM + k] = lo + hi + xb;   // 64B coalesced per 16-lane group
    }
}

// k_upd: contiguous message mean + root matmul + ReLU + GRU.
__global__ void k_upd(const float* __restrict__ cr, const float* __restrict__ cb,
                      const float* __restrict__ wih, const float* __restrict__ whh,
                      const float* __restrict__ bih, const float* __restrict__ bhh,
                      float* __restrict__ outw) {
    __shared__ float s_cr[DIM * DIM];
    __shared__ float s_wih[DIM * 3 * DIM];   // transposed [d][r]
    __shared__ float s_whh[DIM * 3 * DIM];
    __shared__ float s_out[16][DIM];
    __shared__ float s_m[16][DIM];
    int tid = threadIdx.x;
    for (int i = tid; i < DIM * DIM; i += 256) s_cr[i] = cr[i];
    for (int i = tid; i < 3 * DIM * DIM; i += 256) {
        int r = i >> 4, d = i & 15;
        s_wih[d * 48 + r] = wih[i];
        s_whh[d * 48 + r] = whh[i];
    }
    int ln = tid >> 4, k = tid & 15;
    int n = blockIdx.x * 16 + ln;
    float hprev = g_out[n * DIM + k];
    s_out[ln][k] = hprev;
    __syncthreads();

    int beg = g_dst_off[n], end = g_dst_off[n + 1];
    float a0 = 0.0f, a1 = 0.0f;
    int q = beg;
    for (; q + 1 < end; q += 2) {
        a0 += __ldg(&g_msg[q * DIM + k]);
        a1 += __ldg(&g_msg[(q + 1) * DIM + k]);
    }
    if (q < end) a0 += __ldg(&g_msg[q * DIM + k]);
    float acc = (a0 + a1) * g_invdeg[n] + cb[k];
#pragma unroll
    for (int d = 0; d < DIM; ++d) acc += s_out[ln][d] * s_cr[d * DIM + k];
    float m = fmaxf(acc, 0.0f);
    s_m[ln][k] = m;
    __syncthreads();

    float gr = bih[k], gz = bih[k + 16], gn = bih[k + 32];
    float hr = bhh[k], hz = bhh[k + 16], hn = bhh[k + 32];
#pragma unroll
    for (int d = 0; d < DIM; ++d) {
        float md = s_m[ln][d], hd = s_out[ln][d];
        gr += md * s_wih[d * 48 + k];
        gz += md * s_wih[d * 48 + k + 16];
        gn += md * s_wih[d * 48 + k + 32];
        hr += hd * s_whh[d * 48 + k];
        hz += hd * s_whh[d * 48 + k + 16];
        hn += hd * s_whh[d * 48 + k + 32];
    }
    float r = 1.0f / (1.0f + expf(-(gr + hr)));
    float z = 1.0f / (1.0f + expf(-(gz + hz)));
    float nh = tanhf(gn + r * hn);
    outw[n * DIM + k] = (1.0f - z) * nh + z * hprev;
}

// ---------------- host launcher ----------------
extern "C" void kernel_launch(void* const* d_in, const int* in_sizes, int n_in,
                              void* d_out, int out_size) {
    const float* x         = (const float*)d_in[0];
    const int*   ei        = (const int*)  d_in[1];
    const float* ea        = (const float*)d_in[2];
    const float* lin0_w    = (const float*)d_in[3];
    const float* lin0_b    = (const float*)d_in[4];
    const float* nn1_w     = (const float*)d_in[5];
    const float* nn1_b     = (const float*)d_in[6];
    const float* nn2_w     = (const float*)d_in[7];
    const float* nn2_b     = (const float*)d_in[8];
    const float* conv_root = (const float*)d_in[9];
    const float* conv_bias = (const float*)d_in[10];
    const float* w_ih      = (const float*)d_in[11];
    const float* w_hh      = (const float*)d_in[12];
    const float* b_ih      = (const float*)d_in[13];
    const float* b_hh      = (const float*)d_in[14];

    float* outp = nullptr;
    cudaGetSymbolAddress((void**)&outp, g_out);

    k_prep<<<(N_EDGES * DIM) / 256 + (N_NODES * DIM) / 256, 256>>>(
        x, ei, ea, lin0_w, lin0_b, nn1_w, nn1_b);
    k_scan<<<2, 1024>>>();
    k_scatter<<<(N_EDGES + 255) / 256, 256>>>(ei);

    for (int r = 0; r < 6; ++r) {
        k_msg<<<N_NODES / 16, 256>>>(nn2_w, nn2_b);   // launch #4 on r==0 (ncu target)
        k_upd<<<N_NODES / 16, 256>>>(conv_root, conv_bias, w_ih, w_hh, b_ih, b_hh,
                                     r == 5 ? (float*)d_out : outp);
    }
}

// round 5
// speedup vs baseline: 1.0154x; 1.0154x over previous
#include <cuda_runtime.h>
#include <math.h>
#include <stdint.h>

#define N_NODES 12800
#define N_EDGES 204800
#define DIM 16

typedef unsigned long long ull;

// ---------------- scratch (static device memory, no allocs) ----------------
__device__ float g_out[N_NODES * DIM];
__device__ float g_he[N_EDGES * DIM];      // edge hidden, edge order
__device__ float g_hs[N_EDGES * DIM];      // edge hidden, src-sorted order
__device__ int   g_qs[N_EDGES];            // src-sorted slot -> dst-sorted slot
__device__ float g_msg[N_EDGES * DIM];     // messages in dst-sorted order
__device__ int   g_src_cnt[N_NODES];       // zero at load; re-zeroed by k_scatter
__device__ int   g_dst_cnt[N_NODES];
__device__ int   g_src_off[N_NODES + 1];
__device__ int   g_dst_off[N_NODES + 1];
__device__ int   g_src_cur[N_NODES];
__device__ int   g_dst_cur[N_NODES];
__device__ float g_invdeg[N_NODES];

// ---------------- setup ----------------
__global__ void k_prep(const float* __restrict__ x, const int* __restrict__ ei,
                       const float* __restrict__ ea,
                       const float* __restrict__ l0w, const float* __restrict__ l0b,
                       const float* __restrict__ n1w, const float* __restrict__ n1b) {
    int gb = blockIdx.x;
    if (gb < (N_EDGES * DIM) / 256) {
        int i = gb * 256 + threadIdx.x;
        int e = i >> 4, j = i & 15;
        float acc = n1b[j];
#pragma unroll
        for (int c = 0; c < 4; ++c) acc += ea[e * 4 + c] * n1w[j * 4 + c];
        g_he[i] = fmaxf(acc, 0.0f);
        if (j == 0) {
            atomicAdd(&g_src_cnt[ei[e]], 1);
            atomicAdd(&g_dst_cnt[ei[N_EDGES + e]], 1);
        }
    } else {
        int i = (gb - (N_EDGES * DIM) / 256) * 256 + threadIdx.x;
        int n = i >> 4, k = i & 15;
        float acc = l0b[k];
#pragma unroll
        for (int c = 0; c < 3; ++c) acc += x[n * 3 + c] * l0w[k * 3 + c];
        g_out[i] = fmaxf(acc, 0.0f);
    }
}

// Shuffle-based exclusive scan; block 0 = src, block 1 = dst (+invdeg).
__global__ void k_scan() {
    const int PER = 13;
    int which = blockIdx.x;
    int* cnt = which ? g_dst_cnt : g_src_cnt;
    int* off = which ? g_dst_off : g_src_off;
    int* cur = which ? g_dst_cur : g_src_cur;
    int tid = threadIdx.x, lane = tid & 31, wid = tid >> 5;
    int base = tid * PER;
    int c[PER];
    int local = 0;
#pragma unroll
    for (int i = 0; i < PER; ++i) {
        int idx = base + i;
        c[i] = (idx < N_NODES) ? cnt[idx] : 0;
        local += c[i];
    }
    int incl = local;
#pragma unroll
    for (int s = 1; s < 32; s <<= 1) {
        int v = __shfl_up_sync(0xffffffffu, incl, s);
        if (lane >= s) incl += v;
    }
    __shared__ int wsum[32];
    if (lane == 31) wsum[wid] = incl;
    __syncthreads();
    if (wid == 0) {
        int v = wsum[lane];
        int iv = v;
#pragma unroll
        for (int s = 1; s < 32; s <<= 1) {
            int t = __shfl_up_sync(0xffffffffu, iv, s);
            if (lane >= s) iv += t;
        }
        wsum[lane] = iv - v;
    }
    __syncthreads();
    int run = wsum[wid] + (incl - local);
#pragma unroll
    for (int i = 0; i < PER; ++i) {
        int idx = base + i;
        if (idx < N_NODES) {
            off[idx] = run;
            cur[idx] = run;
            if (which) g_invdeg[idx] = 1.0f / fmaxf((float)c[i], 1.0f);
            run += c[i];
        }
    }
    if (tid == 1023) off[N_NODES] = run;
}

// Place each edge: gather h_e into src-sorted order, record its dst slot.
// Re-zeroes count arrays for the next kernel_launch call.
__global__ void k_scatter(const int* __restrict__ ei) {
    int e = blockIdx.x * blockDim.x + threadIdx.x;
    if (e >= N_EDGES) return;
    int s = ei[e], d = ei[N_EDGES + e];
    int p = atomicAdd(&g_src_cur[s], 1);
    int q = atomicAdd(&g_dst_cur[d], 1);
    g_qs[p] = q;
    const float4* hsrc = (const float4*)&g_he[e * DIM];
    float4* hdst = (float4*)&g_hs[p * DIM];
    hdst[0] = hsrc[0]; hdst[1] = hsrc[1]; hdst[2] = hsrc[2]; hdst[3] = hsrc[3];
    if (e < N_NODES) { g_src_cnt[e] = 0; g_dst_cnt[e] = 0; }
}

// ---------------- per-round kernels ----------------
// k_msg: 256 threads = 16 nodes x 16 lanes; lane owns one k.
// P[k][j0..15] kept as 8 packed f32x2 registers. Edge loop is software-
// pipelined (depth 1): loads for edge i+1 issue before the fma chain of i.
__global__ void __launch_bounds__(256) k_msg(const float* __restrict__ w2,
                                             const float* __restrict__ b2) {
    __shared__ ull s_w2p[16 * 8 * 16];   // [d][jj][k], j-pairs packed: 16 KB
    __shared__ float s_b2[256];          // [d][k]
    __shared__ float s_out[16][16];
    int tid = threadIdx.x;
    for (int i = tid; i < 4096; i += 256) {
        int d = i >> 8, k = (i >> 4) & 15, j = i & 15;
        ((float*)&s_w2p[(d * 8 + (j >> 1)) * 16 + k])[j & 1] = w2[i];
    }
    for (int i = tid; i < 256; i += 256) s_b2[i] = b2[i];
    int k = tid & 15, g = tid >> 4;
    int n = blockIdx.x * 16 + g;
    s_out[g][k] = g_out[n * DIM + k];
    __syncthreads();

    ull p2[8];
    float xb = 0.0f;
#pragma unroll
    for (int jj = 0; jj < 8; ++jj) p2[jj] = 0ull;
#pragma unroll
    for (int d = 0; d < 16; ++d) {
        float od = s_out[g][d];
        ull od2;
        asm("mov.b64 %0,{%1,%1};" : "=l"(od2) : "f"(od));
        xb += od * s_b2[d * 16 + k];
#pragma unroll
        for (int jj = 0; jj < 8; ++jj) {
            ull w = s_w2p[(d * 8 + jj) * 16 + k];
            asm("fma.rn.f32x2 %0,%1,%2,%0;" : "+l"(p2[jj]) : "l"(od2), "l"(w));
        }
    }

    int beg = g_src_off[n], end = g_src_off[n + 1];
    const ulonglong2* hsp = (const ulonglong2*)g_hs;
    if (beg < end) {
        int q = __ldg(&g_qs[beg]);
        ulonglong2 A = __ldg(&hsp[beg * 4 + 0]);
        ulonglong2 B = __ldg(&hsp[beg * 4 + 1]);
        ulonglong2 C = __ldg(&hsp[beg * 4 + 2]);
        ulonglong2 D = __ldg(&hsp[beg * 4 + 3]);
#pragma unroll 1
        for (int i = beg; i < end; ++i) {
            int ip = (i + 1 < end) ? i + 1 : i;   // branch-free, in-bounds prefetch
            int qn = __ldg(&g_qs[ip]);
            ulonglong2 An = __ldg(&hsp[ip * 4 + 0]);
            ulonglong2 Bn = __ldg(&hsp[ip * 4 + 1]);
            ulonglong2 Cn = __ldg(&hsp[ip * 4 + 2]);
            ulonglong2 Dn = __ldg(&hsp[ip * 4 + 3]);

            ull acc;
            asm("mul.rn.f32x2 %0,%1,%2;" : "=l"(acc) : "l"(A.x), "l"(p2[0]));
            asm("fma.rn.f32x2 %0,%1,%2,%0;" : "+l"(acc) : "l"(A.y), "l"(p2[1]));
            asm("fma.rn.f32x2 %0,%1,%2,%0;" : "+l"(acc) : "l"(B.x), "l"(p2[2]));
            asm("fma.rn.f32x2 %0,%1,%2,%0;" : "+l"(acc) : "l"(B.y), "l"(p2[3]));
            asm("fma.rn.f32x2 %0,%1,%2,%0;" : "+l"(acc) : "l"(C.x), "l"(p2[4]));
            asm("fma.rn.f32x2 %0,%1,%2,%0;" : "+l"(acc) : "l"(C.y), "l"(p2[5]));
            asm("fma.rn.f32x2 %0,%1,%2,%0;" : "+l"(acc) : "l"(D.x), "l"(p2[6]));
            asm("fma.rn.f32x2 %0,%1,%2,%0;" : "+l"(acc) : "l"(D.y), "l"(p2[7]));
            float lo, hi;
            asm("mov.b64 {%0,%1},%2;" : "=f"(lo), "=f"(hi) : "l"(acc));
            g_msg[q * DIM + k] = lo + hi + xb;

            q = qn; A = An; B = Bn; C = Cn; D = Dn;
        }
    }
}

// k_upd: contiguous message mean (4-way MLP) + root matmul + ReLU + GRU.
__global__ void k_upd(const float* __restrict__ cr, const float* __restrict__ cb,
                      const float* __restrict__ wih, const float* __restrict__ whh,
                      const float* __restrict__ bih, const float* __restrict__ bhh,
                      float* __restrict__ outw) {
    __shared__ float s_cr[DIM * DIM];
    __shared__ float s_wih[DIM * 3 * DIM];   // transposed [d][r]
    __shared__ float s_whh[DIM * 3 * DIM];
    __shared__ float s_out[16][DIM];
    __shared__ float s_m[16][DIM];
    int tid = threadIdx.x;
    for (int i = tid; i < DIM * DIM; i += 256) s_cr[i] = cr[i];
    for (int i = tid; i < 3 * DIM * DIM; i += 256) {
        int r = i >> 4, d = i & 15;
        s_wih[d * 48 + r] = wih[i];
        s_whh[d * 48 + r] = whh[i];
    }
    int ln = tid >> 4, k = tid & 15;
    int n = blockIdx.x * 16 + ln;
    float hprev = g_out[n * DIM + k];
    s_out[ln][k] = hprev;
    __syncthreads();

    int beg = g_dst_off[n], end = g_dst_off[n + 1];
    float a0 = 0.0f, a1 = 0.0f, a2 = 0.0f, a3 = 0.0f;
    int q = beg;
    for (; q + 3 < end; q += 4) {
        a0 += __ldg(&g_msg[(q + 0) * DIM + k]);
        a1 += __ldg(&g_msg[(q + 1) * DIM + k]);
        a2 += __ldg(&g_msg[(q + 2) * DIM + k]);
        a3 += __ldg(&g_msg[(q + 3) * DIM + k]);
    }
    for (; q < end; ++q) a0 += __ldg(&g_msg[q * DIM + k]);
    float acc = ((a0 + a1) + (a2 + a3)) * g_invdeg[n] + cb[k];
#pragma unroll
    for (int d = 0; d < DIM; ++d) acc += s_out[ln][d] * s_cr[d * DIM + k];
    float m = fmaxf(acc, 0.0f);
    s_m[ln][k] = m;
    __syncthreads();

    float gr = bih[k], gz = bih[k + 16], gn = bih[k + 32];
    float hr = bhh[k], hz = bhh[k + 16], hn = bhh[k + 32];
#pragma unroll
    for (int d = 0; d < DIM; ++d) {
        float md = s_m[ln][d], hd = s_out[ln][d];
        gr += md * s_wih[d * 48 + k];
        gz += md * s_wih[d * 48 + k + 16];
        gn += md * s_wih[d * 48 + k + 32];
        hr += hd * s_whh[d * 48 + k];
        hz += hd * s_whh[d * 48 + k + 16];
        hn += hd * s_whh[d * 48 + k + 32];
    }
    float r = 1.0f / (1.0f + expf(-(gr + hr)));
    float z = 1.0f / (1.0f + expf(-(gz + hz)));
    float nh = tanhf(gn + r * hn);
    outw[n * DIM + k] = (1.0f - z) * nh + z * hprev;
}

// ---------------- host launcher ----------------
extern "C" void kernel_launch(void* const* d_in, const int* in_sizes, int n_in,
                              void* d_out, int out_size) {
    const float* x         = (const float*)d_in[0];
    const int*   ei        = (const int*)  d_in[1];
    const float* ea        = (const float*)d_in[2];
    const float* lin0_w    = (const float*)d_in[3];
    const float* lin0_b    = (const float*)d_in[4];
    const float* nn1_w     = (const float*)d_in[5];
    const float* nn1_b     = (const float*)d_in[6];
    const float* nn2_w     = (const float*)d_in[7];
    const float* nn2_b     = (const float*)d_in[8];
    const float* conv_root = (const float*)d_in[9];
    const float* conv_bias = (const float*)d_in[10];
    const float* w_ih      = (const float*)d_in[11];
    const float* w_hh      = (const float*)d_in[12];
    const float* b_ih      = (const float*)d_in[13];
    const float* b_hh      = (const float*)d_in[14];

    float* outp = nullptr;
    cudaGetSymbolAddress((void**)&outp, g_out);

    k_prep<<<(N_EDGES * DIM) / 256 + (N_NODES * DIM) / 256, 256>>>(
        x, ei, ea, lin0_w, lin0_b, nn1_w, nn1_b);
    k_scan<<<2, 1024>>>();
    k_scatter<<<(N_EDGES + 255) / 256, 256>>>(ei);

    for (int r = 0; r < 6; ++r) {
        k_msg<<<N_NODES / 16, 256>>>(nn2_w, nn2_b);   // launch #4 on r==0 (ncu target)
        k_upd<<<N_NODES / 16, 256>>>(conv_root, conv_bias, w_ih, w_hh, b_ih, b_hh,
                                     r == 5 ? (float*)d_out : outp);
    }
}

// round 6
// speedup vs baseline: 1.1553x; 1.1378x over previous
#include <cuda_runtime.h>
#include <math.h>
#include <stdint.h>

#define N_NODES 12800
#define N_EDGES 204800
#define DIM 16

typedef unsigned long long ull;

// ---------------- scratch (static device memory, no allocs) ----------------
__device__ float g_out[N_NODES * DIM];
__device__ float g_he[N_EDGES * DIM];      // edge hidden, edge order
__device__ float g_hs[N_EDGES * DIM];      // edge hidden, src-sorted order
__device__ int   g_qs[N_EDGES];            // src-sorted slot -> dst-sorted slot
__device__ float g_msg[N_EDGES * DIM];     // messages in dst-sorted order
__device__ int   g_src_cnt[N_NODES];       // zero at load; re-zeroed by k_scatter
__device__ int   g_dst_cnt[N_NODES];
__device__ int   g_src_off[N_NODES + 1];
__device__ int   g_dst_off[N_NODES + 1];
__device__ int   g_src_cur[N_NODES];
__device__ int   g_dst_cur[N_NODES];
__device__ float g_invdeg[N_NODES];

// ---------------- setup ----------------
__global__ void k_prep(const float* __restrict__ x, const int* __restrict__ ei,
                       const float* __restrict__ ea,
                       const float* __restrict__ l0w, const float* __restrict__ l0b,
                       const float* __restrict__ n1w, const float* __restrict__ n1b) {
    int gb = blockIdx.x;
    if (gb < (N_EDGES * DIM) / 256) {
        int i = gb * 256 + threadIdx.x;
        int e = i >> 4, j = i & 15;
        float acc = n1b[j];
#pragma unroll
        for (int c = 0; c < 4; ++c) acc += ea[e * 4 + c] * n1w[j * 4 + c];
        g_he[i] = fmaxf(acc, 0.0f);
        if (j == 0) {
            atomicAdd(&g_src_cnt[ei[e]], 1);
            atomicAdd(&g_dst_cnt[ei[N_EDGES + e]], 1);
        }
    } else {
        int i = (gb - (N_EDGES * DIM) / 256) * 256 + threadIdx.x;
        int n = i >> 4, k = i & 15;
        float acc = l0b[k];
#pragma unroll
        for (int c = 0; c < 3; ++c) acc += x[n * 3 + c] * l0w[k * 3 + c];
        g_out[i] = fmaxf(acc, 0.0f);
    }
}

// Shuffle-based exclusive scan; block 0 = src, block 1 = dst (+invdeg).
__global__ void k_scan() {
    const int PER = 13;
    int which = blockIdx.x;
    int* cnt = which ? g_dst_cnt : g_src_cnt;
    int* off = which ? g_dst_off : g_src_off;
    int* cur = which ? g_dst_cur : g_src_cur;
    int tid = threadIdx.x, lane = tid & 31, wid = tid >> 5;
    int base = tid * PER;
    int c[PER];
    int local = 0;
#pragma unroll
    for (int i = 0; i < PER; ++i) {
        int idx = base + i;
        c[i] = (idx < N_NODES) ? cnt[idx] : 0;
        local += c[i];
    }
    int incl = local;
#pragma unroll
    for (int s = 1; s < 32; s <<= 1) {
        int v = __shfl_up_sync(0xffffffffu, incl, s);
        if (lane >= s) incl += v;
    }
    __shared__ int wsum[32];
    if (lane == 31) wsum[wid] = incl;
    __syncthreads();
    if (wid == 0) {
        int v = wsum[lane];
        int iv = v;
#pragma unroll
        for (int s = 1; s < 32; s <<= 1) {
            int t = __shfl_up_sync(0xffffffffu, iv, s);
            if (lane >= s) iv += t;
        }
        wsum[lane] = iv - v;
    }
    __syncthreads();
    int run = wsum[wid] + (incl - local);
#pragma unroll
    for (int i = 0; i < PER; ++i) {
        int idx = base + i;
        if (idx < N_NODES) {
            off[idx] = run;
            cur[idx] = run;
            if (which) g_invdeg[idx] = 1.0f / fmaxf((float)c[i], 1.0f);
            run += c[i];
        }
    }
    if (tid == 1023) off[N_NODES] = run;
}

// Place each edge: gather h_e into src-sorted order, record its dst slot.
// Re-zeroes count arrays for the next kernel_launch call.
__global__ void k_scatter(const int* __restrict__ ei) {
    int e = blockIdx.x * blockDim.x + threadIdx.x;
    if (e >= N_EDGES) return;
    int s = ei[e], d = ei[N_EDGES + e];
    int p = atomicAdd(&g_src_cur[s], 1);
    int q = atomicAdd(&g_dst_cur[d], 1);
    g_qs[p] = q;
    const float4* hsrc = (const float4*)&g_he[e * DIM];
    float4* hdst = (float4*)&g_hs[p * DIM];
    hdst[0] = hsrc[0]; hdst[1] = hsrc[1]; hdst[2] = hsrc[2]; hdst[3] = hsrc[3];
    if (e < N_NODES) { g_src_cnt[e] = 0; g_dst_cnt[e] = 0; }
}

// ---------------- per-round kernels ----------------
// k_msg: 256 threads = 16 nodes x 16 lanes; lane owns one k.
// Prologue: P[k][j-pairs] in 8 f32x2 regs (w2 staged in smem).
// Mainloop: block's contiguous src-sorted edge range in 128-edge chunks;
// chunk h+q cooperatively staged in smem (aliasing the dead w2 buffer),
// groups consume via broadcast LDS. Each edge's data hits L1tex ONCE.
#define CHUNK 128
__global__ void __launch_bounds__(256) k_msg(const float* __restrict__ w2,
                                             const float* __restrict__ b2) {
    __shared__ __align__(16) char s_raw[16384];   // w2 packed, then h chunks
    __shared__ float s_b2[256];
    __shared__ float s_out[16][16];
    __shared__ int s_q[CHUNK];
    ull* s_w2p = (ull*)s_raw;                     // [d][jj][k]
    const ulonglong2* s_h2 = (const ulonglong2*)s_raw;
    float4* s_h4 = (float4*)s_raw;

    int tid = threadIdx.x;
    for (int i = tid; i < 4096; i += 256) {
        int d = i >> 8, k = (i >> 4) & 15, j = i & 15;
        ((float*)&s_w2p[(d * 8 + (j >> 1)) * 16 + k])[j & 1] = w2[i];
    }
    s_b2[tid] = b2[tid];
    int k = tid & 15, g = tid >> 4;
    int n = blockIdx.x * 16 + g;
    s_out[g][k] = g_out[n * DIM + k];
    __syncthreads();

    ull p2[8];
    float xb = 0.0f;
#pragma unroll
    for (int jj = 0; jj < 8; ++jj) p2[jj] = 0ull;
#pragma unroll
    for (int d = 0; d < 16; ++d) {
        float od = s_out[g][d];
        ull od2;
        asm("mov.b64 %0,{%1,%1};" : "=l"(od2) : "f"(od));
        xb += od * s_b2[d * 16 + k];
#pragma unroll
        for (int jj = 0; jj < 8; ++jj) {
            ull w = s_w2p[(d * 8 + jj) * 16 + k];
            asm("fma.rn.f32x2 %0,%1,%2,%0;" : "+l"(p2[jj]) : "l"(od2), "l"(w));
        }
    }

    int bn = g_src_off[n], en = g_src_off[n + 1];
    int E0 = g_src_off[blockIdx.x * 16];
    int E1 = g_src_off[blockIdx.x * 16 + 16];
    const float4* hs4 = (const float4*)g_hs;

    for (int cb = E0; cb < E1; cb += CHUNK) {
        int ce = cb + CHUNK < E1 ? cb + CHUNK : E1;
        __syncthreads();                          // w2 reads / prior chunk done
        int cnt4 = (ce - cb) * 4;
        for (int i4 = tid; i4 < cnt4; i4 += 256)
            s_h4[i4] = hs4[cb * 4 + i4];          // coalesced, once per edge
        if (tid < ce - cb) s_q[tid] = g_qs[cb + tid];
        __syncthreads();

        int lo = bn > cb ? bn : cb;
        int hi = en < ce ? en : ce;
        for (int i = lo; i < hi; ++i) {
            int li = i - cb;
            int q = s_q[li];                      // broadcast LDS
            ulonglong2 A = s_h2[li * 4 + 0];      // broadcast LDS.128 x4
            ulonglong2 B = s_h2[li * 4 + 1];
            ulonglong2 C = s_h2[li * 4 + 2];
            ulonglong2 D = s_h2[li * 4 + 3];
            ull a0, a1;
            asm("mul.rn.f32x2 %0,%1,%2;" : "=l"(a0) : "l"(A.x), "l"(p2[0]));
            asm("fma.rn.f32x2 %0,%1,%2,%0;" : "+l"(a0) : "l"(A.y), "l"(p2[1]));
            asm("fma.rn.f32x2 %0,%1,%2,%0;" : "+l"(a0) : "l"(B.x), "l"(p2[2]));
            asm("fma.rn.f32x2 %0,%1,%2,%0;" : "+l"(a0) : "l"(B.y), "l"(p2[3]));
            asm("mul.rn.f32x2 %0,%1,%2;" : "=l"(a1) : "l"(C.x), "l"(p2[4]));
            asm("fma.rn.f32x2 %0,%1,%2,%0;" : "+l"(a1) : "l"(C.y), "l"(p2[5]));
            asm("fma.rn.f32x2 %0,%1,%2,%0;" : "+l"(a1) : "l"(D.x), "l"(p2[6]));
            asm("fma.rn.f32x2 %0,%1,%2,%0;" : "+l"(a1) : "l"(D.y), "l"(p2[7]));
            asm("add.rn.f32x2 %0,%0,%1;" : "+l"(a0) : "l"(a1));
            float lo_f, hi_f;
            asm("mov.b64 {%0,%1},%2;" : "=f"(lo_f), "=f"(hi_f) : "l"(a0));
            g_msg[q * DIM + k] = lo_f + hi_f + xb;
        }
    }
}

// k_upd: contiguous message mean (4-way MLP) + root matmul + ReLU + GRU.
__global__ void k_upd(const float* __restrict__ cr, const float* __restrict__ cb,
                      const float* __restrict__ wih, const float* __restrict__ whh,
                      const float* __restrict__ bih, const float* __restrict__ bhh,
                      float* __restrict__ outw) {
    __shared__ float s_cr[DIM * DIM];
    __shared__ float s_wih[DIM * 3 * DIM];   // transposed [d][r]
    __shared__ float s_whh[DIM * 3 * DIM];
    __shared__ float s_out[16][DIM];
    __shared__ float s_m[16][DIM];
    int tid = threadIdx.x;
    for (int i = tid; i < DIM * DIM; i += 256) s_cr[i] = cr[i];
    for (int i = tid; i < 3 * DIM * DIM; i += 256) {
        int r = i >> 4, d = i & 15;
        s_wih[d * 48 + r] = wih[i];
        s_whh[d * 48 + r] = whh[i];
    }
    int ln = tid >> 4, k = tid & 15;
    int n = blockIdx.x * 16 + ln;
    float hprev = g_out[n * DIM + k];
    s_out[ln][k] = hprev;
    __syncthreads();

    int beg = g_dst_off[n], end = g_dst_off[n + 1];
    float a0 = 0.0f, a1 = 0.0f, a2 = 0.0f, a3 = 0.0f;
    int q = beg;
    for (; q + 3 < end; q += 4) {
        a0 += __ldg(&g_msg[(q + 0) * DIM + k]);
        a1 += __ldg(&g_msg[(q + 1) * DIM + k]);
        a2 += __ldg(&g_msg[(q + 2) * DIM + k]);
        a3 += __ldg(&g_msg[(q + 3) * DIM + k]);
    }
    for (; q < end; ++q) a0 += __ldg(&g_msg[q * DIM + k]);
    float acc = ((a0 + a1) + (a2 + a3)) * g_invdeg[n] + cb[k];
#pragma unroll
    for (int d = 0; d < DIM; ++d) acc += s_out[ln][d] * s_cr[d * DIM + k];
    float m = fmaxf(acc, 0.0f);
    s_m[ln][k] = m;
    __syncthreads();

    float gr = bih[k], gz = bih[k + 16], gn = bih[k + 32];
    float hr = bhh[k], hz = bhh[k + 16], hn = bhh[k + 32];
#pragma unroll
    for (int d = 0; d < DIM; ++d) {
        float md = s_m[ln][d], hd = s_out[ln][d];
        gr += md * s_wih[d * 48 + k];
        gz += md * s_wih[d * 48 + k + 16];
        gn += md * s_wih[d * 48 + k + 32];
        hr += hd * s_whh[d * 48 + k];
        hz += hd * s_whh[d * 48 + k + 16];
        hn += hd * s_whh[d * 48 + k + 32];
    }
    float r = 1.0f / (1.0f + expf(-(gr + hr)));
    float z = 1.0f / (1.0f + expf(-(gz + hz)));
    float nh = tanhf(gn + r * hn);
    outw[n * DIM + k] = (1.0f - z) * nh + z * hprev;
}

// ---------------- host launcher ----------------
extern "C" void kernel_launch(void* const* d_in, const int* in_sizes, int n_in,
                              void* d_out, int out_size) {
    const float* x         = (const float*)d_in[0];
    const int*   ei        = (const int*)  d_in[1];
    const float* ea        = (const float*)d_in[2];
    const float* lin0_w    = (const float*)d_in[3];
    const float* lin0_b    = (const float*)d_in[4];
    const float* nn1_w     = (const float*)d_in[5];
    const float* nn1_b     = (const float*)d_in[6];
    const float* nn2_w     = (const float*)d_in[7];
    const float* nn2_b     = (const float*)d_in[8];
    const float* conv_root = (const float*)d_in[9];
    const float* conv_bias = (const float*)d_in[10];
    const float* w_ih      = (const float*)d_in[11];
    const float* w_hh      = (const float*)d_in[12];
    const float* b_ih      = (const float*)d_in[13];
    const float* b_hh      = (const float*)d_in[14];

    float* outp = nullptr;
    cudaGetSymbolAddress((void**)&outp, g_out);

    k_prep<<<(N_EDGES * DIM) / 256 + (N_NODES * DIM) / 256, 256>>>(
        x, ei, ea, lin0_w, lin0_b, nn1_w, nn1_b);
    k_scan<<<2, 1024>>>();
    k_scatter<<<(N_EDGES + 255) / 256, 256>>>(ei);

    for (int r = 0; r < 6; ++r) {
        k_msg<<<N_NODES / 16, 256>>>(nn2_w, nn2_b);   // launch #4 on r==0 (ncu target)
        k_upd<<<N_NODES / 16, 256>>>(conv_root, conv_bias, w_ih, w_hh, b_ih, b_hh,
                                     r == 5 ? (float*)d_out : outp);
    }
}

// round 7
// speedup vs baseline: 1.1731x; 1.0155x over previous
#include <cuda_runtime.h>
#include <math.h>
#include <stdint.h>

#define N_NODES 12800
#define N_EDGES 204800
#define DIM 16
#define CHUNK 256

typedef unsigned long long ull;

// ---------------- scratch (static device memory, no allocs) ----------------
__device__ float g_out[N_NODES * DIM];
__device__ float g_he[N_EDGES * DIM];       // edge hidden, edge order
__device__ float g_hs[N_EDGES * DIM];       // edge hidden, src-sorted order
__device__ int   g_qs[N_EDGES];             // src-sorted slot -> dst-sorted slot
__device__ float g_msg0[N_EDGES * DIM];     // message ping-pong buffers
__device__ float g_msg1[N_EDGES * DIM];
__device__ int   g_src_cnt[N_NODES];        // zero at load; re-zeroed by k_scatter
__device__ int   g_dst_cnt[N_NODES];
__device__ int   g_src_off[N_NODES + 1];
__device__ int   g_dst_off[N_NODES + 1];
__device__ int   g_src_cur[N_NODES];
__device__ int   g_dst_cur[N_NODES];
__device__ float g_invdeg[N_NODES];

// ---------------- setup ----------------
__global__ void k_prep(const float* __restrict__ x, const int* __restrict__ ei,
                       const float* __restrict__ ea,
                       const float* __restrict__ l0w, const float* __restrict__ l0b,
                       const float* __restrict__ n1w, const float* __restrict__ n1b) {
    int gb = blockIdx.x;
    if (gb < (N_EDGES * DIM) / 256) {
        int i = gb * 256 + threadIdx.x;
        int e = i >> 4, j = i & 15;
        float acc = n1b[j];
#pragma unroll
        for (int c = 0; c < 4; ++c) acc += ea[e * 4 + c] * n1w[j * 4 + c];
        g_he[i] = fmaxf(acc, 0.0f);
        if (j == 0) {
            atomicAdd(&g_src_cnt[ei[e]], 1);
            atomicAdd(&g_dst_cnt[ei[N_EDGES + e]], 1);
        }
    } else {
        int i = (gb - (N_EDGES * DIM) / 256) * 256 + threadIdx.x;
        int n = i >> 4, k = i & 15;
        float acc = l0b[k];
#pragma unroll
        for (int c = 0; c < 3; ++c) acc += x[n * 3 + c] * l0w[k * 3 + c];
        g_out[i] = fmaxf(acc, 0.0f);
    }
}

// Shuffle-based exclusive scan; block 0 = src, block 1 = dst (+invdeg).
__global__ void k_scan() {
    const int PER = 13;
    int which = blockIdx.x;
    int* cnt = which ? g_dst_cnt : g_src_cnt;
    int* off = which ? g_dst_off : g_src_off;
    int* cur = which ? g_dst_cur : g_src_cur;
    int tid = threadIdx.x, lane = tid & 31, wid = tid >> 5;
    int base = tid * PER;
    int c[PER];
    int local = 0;
#pragma unroll
    for (int i = 0; i < PER; ++i) {
        int idx = base + i;
        c[i] = (idx < N_NODES) ? cnt[idx] : 0;
        local += c[i];
    }
    int incl = local;
#pragma unroll
    for (int s = 1; s < 32; s <<= 1) {
        int v = __shfl_up_sync(0xffffffffu, incl, s);
        if (lane >= s) incl += v;
    }
    __shared__ int wsum[32];
    if (lane == 31) wsum[wid] = incl;
    __syncthreads();
    if (wid == 0) {
        int v = wsum[lane];
        int iv = v;
#pragma unroll
        for (int s = 1; s < 32; s <<= 1) {
            int t = __shfl_up_sync(0xffffffffu, iv, s);
            if (lane >= s) iv += t;
        }
        wsum[lane] = iv - v;
    }
    __syncthreads();
    int run = wsum[wid] + (incl - local);
#pragma unroll
    for (int i = 0; i < PER; ++i) {
        int idx = base + i;
        if (idx < N_NODES) {
            off[idx] = run;
            cur[idx] = run;
            if (which) g_invdeg[idx] = 1.0f / fmaxf((float)c[i], 1.0f);
            run += c[i];
        }
    }
    if (tid == 1023) off[N_NODES] = run;
}

// Place each edge: gather h_e into src-sorted order, record its dst slot.
// Re-zeroes count arrays for the next kernel_launch call.
__global__ void k_scatter(const int* __restrict__ ei) {
    int e = blockIdx.x * blockDim.x + threadIdx.x;
    if (e >= N_EDGES) return;
    int s = ei[e], d = ei[N_EDGES + e];
    int p = atomicAdd(&g_src_cur[s], 1);
    int q = atomicAdd(&g_dst_cur[d], 1);
    g_qs[p] = q;
    const float4* hsrc = (const float4*)&g_he[e * DIM];
    float4* hdst = (float4*)&g_hs[p * DIM];
    hdst[0] = hsrc[0]; hdst[1] = hsrc[1]; hdst[2] = hsrc[2]; hdst[3] = hsrc[3];
    if (e < N_NODES) { g_src_cnt[e] = 0; g_dst_cnt[e] = 0; }
}

// ---------------- fused per-round kernel ----------------
// Block = 16 nodes x 16 lanes. Phase 1 (r>0): read prev messages (contiguous,
// dst-sorted), mean + root matmul + ReLU + GRU -> new out (smem + g_out).
// Phase 2: P in 8 f32x2 regs per lane. Phase 3: stream block's src-sorted
// edges in 256-edge chunks staged in smem (aliasing dead w2 buffer),
// store messages to msg_w at dst-sorted slots.
__global__ void __launch_bounds__(256) k_round(
    const float* __restrict__ w2, const float* __restrict__ b2,
    const float* __restrict__ cr, const float* __restrict__ cb,
    const float* __restrict__ wih, const float* __restrict__ whh,
    const float* __restrict__ bih, const float* __restrict__ bhh,
    const float* __restrict__ msg_r, float* __restrict__ msg_w, int r) {
    __shared__ __align__(16) char s_raw[16384];   // w2 packed, then h chunks
    __shared__ float s_b2[256];
    __shared__ float s_cr[256];
    __shared__ float s_wih[768];                  // transposed [d][gate]
    __shared__ float s_whh[768];
    __shared__ float s_out[16][16];
    __shared__ float s_m[16][16];
    __shared__ int s_q[CHUNK];
    ull* s_w2p = (ull*)s_raw;                     // [d][jj][k]
    const ulonglong2* s_h2 = (const ulonglong2*)s_raw;
    float4* s_h4 = (float4*)s_raw;

    int tid = threadIdx.x;
    int k = tid & 15, g = tid >> 4;
    int n = blockIdx.x * 16 + g;

    for (int i = tid; i < 4096; i += 256) {
        int d = i >> 8, kk = (i >> 4) & 15, j = i & 15;
        ((float*)&s_w2p[(d * 8 + (j >> 1)) * 16 + kk])[j & 1] = w2[i];
    }
    s_b2[tid] = b2[tid];
    s_cr[tid] = cr[tid];
    for (int i = tid; i < 768; i += 256) {
        int rr = i >> 4, d = i & 15;
        s_wih[d * 48 + rr] = wih[i];
        s_whh[d * 48 + rr] = whh[i];
    }
    float hprev = g_out[n * DIM + k];
    s_out[g][k] = hprev;
    __syncthreads();

    if (r > 0) {
        // ---- fused update: mean(prev msgs) + root + ReLU + GRU ----
        int beg = g_dst_off[n], end = g_dst_off[n + 1];
        float a0 = 0.0f, a1 = 0.0f, a2 = 0.0f, a3 = 0.0f;
        int q = beg;
        for (; q + 3 < end; q += 4) {
            a0 += __ldg(&msg_r[(q + 0) * DIM + k]);
            a1 += __ldg(&msg_r[(q + 1) * DIM + k]);
            a2 += __ldg(&msg_r[(q + 2) * DIM + k]);
            a3 += __ldg(&msg_r[(q + 3) * DIM + k]);
        }
        for (; q < end; ++q) a0 += __ldg(&msg_r[q * DIM + k]);
        float acc = ((a0 + a1) + (a2 + a3)) * g_invdeg[n] + cb[k];
#pragma unroll
        for (int d = 0; d < DIM; ++d) acc += s_out[g][d] * s_cr[d * 16 + k];
        float m = fmaxf(acc, 0.0f);
        s_m[g][k] = m;
        __syncthreads();

        float gr = bih[k], gz = bih[k + 16], gn = bih[k + 32];
        float hr = bhh[k], hz = bhh[k + 16], hn = bhh[k + 32];
#pragma unroll
        for (int d = 0; d < DIM; ++d) {
            float md = s_m[g][d], hd = s_out[g][d];
            gr += md * s_wih[d * 48 + k];
            gz += md * s_wih[d * 48 + k + 16];
            gn += md * s_wih[d * 48 + k + 32];
            hr += hd * s_whh[d * 48 + k];
            hz += hd * s_whh[d * 48 + k + 16];
            hn += hd * s_whh[d * 48 + k + 32];
        }
        float rr = 1.0f / (1.0f + expf(-(gr + hr)));
        float zz = 1.0f / (1.0f + expf(-(gz + hz)));
        float nh = tanhf(gn + rr * hn);
        float hnew = (1.0f - zz) * nh + zz * hprev;
        __syncthreads();                 // all reads of s_out complete
        s_out[g][k] = hnew;
        g_out[n * DIM + k] = hnew;
        __syncthreads();
    }

    // ---- P-compute: P[k][j-pairs] in 8 f32x2 regs ----
    ull p2[8];
    float xb = 0.0f;
#pragma unroll
    for (int jj = 0; jj < 8; ++jj) p2[jj] = 0ull;
#pragma unroll
    for (int d = 0; d < 16; ++d) {
        float od = s_out[g][d];
        ull od2;
        asm("mov.b64 %0,{%1,%1};" : "=l"(od2) : "f"(od));
        xb += od * s_b2[d * 16 + k];
#pragma unroll
        for (int jj = 0; jj < 8; ++jj) {
            ull w = s_w2p[(d * 8 + jj) * 16 + k];
            asm("fma.rn.f32x2 %0,%1,%2,%0;" : "+l"(p2[jj]) : "l"(od2), "l"(w));
        }
    }

    // ---- edge mainloop ----
    int bn = g_src_off[n], en = g_src_off[n + 1];
    int E0 = g_src_off[blockIdx.x * 16];
    int E1 = g_src_off[blockIdx.x * 16 + 16];
    const float4* hs4 = (const float4*)g_hs;

    for (int cbase = E0; cbase < E1; cbase += CHUNK) {
        int ce = cbase + CHUNK < E1 ? cbase + CHUNK : E1;
        __syncthreads();                          // w2 reads / prior chunk done
        int cnt4 = (ce - cbase) * 4;
        for (int i4 = tid; i4 < cnt4; i4 += 256)
            s_h4[i4] = hs4[cbase * 4 + i4];       // coalesced, once per edge
        if (tid < ce - cbase) s_q[tid] = g_qs[cbase + tid];
        __syncthreads();

        int lo = bn > cbase ? bn : cbase;
        int hi = en < ce ? en : ce;
        for (int i = lo; i < hi; ++i) {
            int li = i - cbase;
            int q = s_q[li];                      // broadcast LDS
            ulonglong2 A = s_h2[li * 4 + 0];      // broadcast LDS.128 x4
            ulonglong2 B = s_h2[li * 4 + 1];
            ulonglong2 C = s_h2[li * 4 + 2];
            ulonglong2 D = s_h2[li * 4 + 3];
            ull a0, a1;
            asm("mul.rn.f32x2 %0,%1,%2;" : "=l"(a0) : "l"(A.x), "l"(p2[0]));
            asm("fma.rn.f32x2 %0,%1,%2,%0;" : "+l"(a0) : "l"(A.y), "l"(p2[1]));
            asm("fma.rn.f32x2 %0,%1,%2,%0;" : "+l"(a0) : "l"(B.x), "l"(p2[2]));
            asm("fma.rn.f32x2 %0,%1,%2,%0;" : "+l"(a0) : "l"(B.y), "l"(p2[3]));
            asm("mul.rn.f32x2 %0,%1,%2;" : "=l"(a1) : "l"(C.x), "l"(p2[4]));
            asm("fma.rn.f32x2 %0,%1,%2,%0;" : "+l"(a1) : "l"(C.y), "l"(p2[5]));
            asm("fma.rn.f32x2 %0,%1,%2,%0;" : "+l"(a1) : "l"(D.x), "l"(p2[6]));
            asm("fma.rn.f32x2 %0,%1,%2,%0;" : "+l"(a1) : "l"(D.y), "l"(p2[7]));
            asm("add.rn.f32x2 %0,%0,%1;" : "+l"(a0) : "l"(a1));
            float lo_f, hi_f;
            asm("mov.b64 {%0,%1},%2;" : "=f"(lo_f), "=f"(hi_f) : "l"(a0));
            msg_w[q * DIM + k] = lo_f + hi_f + xb;
        }
    }
}

// ---------------- final GRU-only kernel -> d_out ----------------
__global__ void k_fin(const float* __restrict__ msg_r,
                      const float* __restrict__ cr, const float* __restrict__ cb,
                      const float* __restrict__ wih, const float* __restrict__ whh,
                      const float* __restrict__ bih, const float* __restrict__ bhh,
                      float* __restrict__ outw) {
    __shared__ float s_cr[DIM * DIM];
    __shared__ float s_wih[DIM * 3 * DIM];
    __shared__ float s_whh[DIM * 3 * DIM];
    __shared__ float s_out[16][DIM];
    __shared__ float s_m[16][DIM];
    int tid = threadIdx.x;
    for (int i = tid; i < DIM * DIM; i += 256) s_cr[i] = cr[i];
    for (int i = tid; i < 3 * DIM * DIM; i += 256) {
        int r = i >> 4, d = i & 15;
        s_wih[d * 48 + r] = wih[i];
        s_whh[d * 48 + r] = whh[i];
    }
    int ln = tid >> 4, k = tid & 15;
    int n = blockIdx.x * 16 + ln;
    float hprev = g_out[n * DIM + k];
    s_out[ln][k] = hprev;
    __syncthreads();

    int beg = g_dst_off[n], end = g_dst_off[n + 1];
    float a0 = 0.0f, a1 = 0.0f, a2 = 0.0f, a3 = 0.0f;
    int q = beg;
    for (; q + 3 < end; q += 4) {
        a0 += __ldg(&msg_r[(q + 0) * DIM + k]);
        a1 += __ldg(&msg_r[(q + 1) * DIM + k]);
        a2 += __ldg(&msg_r[(q + 2) * DIM + k]);
        a3 += __ldg(&msg_r[(q + 3) * DIM + k]);
    }
    for (; q < end; ++q) a0 += __ldg(&msg_r[q * DIM + k]);
    float acc = ((a0 + a1) + (a2 + a3)) * g_invdeg[n] + cb[k];
#pragma unroll
    for (int d = 0; d < DIM; ++d) acc += s_out[ln][d] * s_cr[d * DIM + k];
    float m = fmaxf(acc, 0.0f);
    s_m[ln][k] = m;
    __syncthreads();

    float gr = bih[k], gz = bih[k + 16], gn = bih[k + 32];
    float hr = bhh[k], hz = bhh[k + 16], hn = bhh[k + 32];
#pragma unroll
    for (int d = 0; d < DIM; ++d) {
        float md = s_m[ln][d], hd = s_out[ln][d];
        gr += md * s_wih[d * 48 + k];
        gz += md * s_wih[d * 48 + k + 16];
        gn += md * s_wih[d * 48 + k + 32];
        hr += hd * s_whh[d * 48 + k];
        hz += hd * s_whh[d * 48 + k + 16];
        hn += hd * s_whh[d * 48 + k + 32];
    }
    float r = 1.0f / (1.0f + expf(-(gr + hr)));
    float z = 1.0f / (1.0f + expf(-(gz + hz)));
    float nh = tanhf(gn + r * hn);
    outw[n * DIM + k] = (1.0f - z) * nh + z * hprev;
}

// ---------------- host launcher ----------------
extern "C" void kernel_launch(void* const* d_in, const int* in_sizes, int n_in,
                              void* d_out, int out_size) {
    const float* x         = (const float*)d_in[0];
    const int*   ei        = (const int*)  d_in[1];
    const float* ea        = (const float*)d_in[2];
    const float* lin0_w    = (const float*)d_in[3];
    const float* lin0_b    = (const float*)d_in[4];
    const float* nn1_w     = (const float*)d_in[5];
    const float* nn1_b     = (const float*)d_in[6];
    const float* nn2_w     = (const float*)d_in[7];
    const float* nn2_b     = (const float*)d_in[8];
    const float* conv_root = (const float*)d_in[9];
    const float* conv_bias = (const float*)d_in[10];
    const float* w_ih      = (const float*)d_in[11];
    const float* w_hh      = (const float*)d_in[12];
    const float* b_ih      = (const float*)d_in[13];
    const float* b_hh      = (const float*)d_in[14];

    float *m0 = nullptr, *m1 = nullptr;
    cudaGetSymbolAddress((void**)&m0, g_msg0);
    cudaGetSymbolAddress((void**)&m1, g_msg1);

    k_prep<<<(N_EDGES * DIM) / 256 + (N_NODES * DIM) / 256, 256>>>(
        x, ei, ea, lin0_w, lin0_b, nn1_w, nn1_b);
    k_scan<<<2, 1024>>>();
    k_scatter<<<(N_EDGES + 255) / 256, 256>>>(ei);

    for (int r = 0; r < 6; ++r) {
        const float* mr = ((r - 1) & 1) ? m1 : m0;   // buffer written by round r-1
        float* mw = (r & 1) ? m1 : m0;
        k_round<<<N_NODES / 16, 256>>>(nn2_w, nn2_b, conv_root, conv_bias,
                                       w_ih, w_hh, b_ih, b_hh, mr, mw, r);
    }
    k_fin<<<N_NODES / 16, 256>>>(m1, conv_root, conv_bias, w_ih, w_hh,
                                 b_ih, b_hh, (float*)d_out);
}